// round 16
// baseline (speedup 1.0000x reference)
#include <cuda_runtime.h>
#include <cuda_bf16.h>
#include <math.h>
#include <stdint.h>

// Problem dims
#define NB   32
#define NTX  128
#define NTY  64
#define NV   50000
#define ND   128
#define NH   256
#define NG4  1024
#define NSTEPS (NTX + NTY)
#define NBLK 128

// Projection tiling
#define MT   128
#define NT   128
#define NMT  16
#define NNT  ((NV + NT - 1) / NT)     // 391
#define NGP  9                        // 144 CTAs, single wave

// proj smem layout (bytes from dynamic smem base)
#define APITCH    528
#define ASPLIT    (128 * APITCH)
#define B_OFF     (2 * ASPLIT)
#define BROWP     80
#define BSEG      (32 * BROWP)
#define BWARP     (4 * BSEG)
#define PROJ_SMEM (B_OFF + 8 * BWARP) // 217088

// ---------------- scratch (device globals) ----------------------------------
__device__ float g_ht[2 * NH * NB];
__device__ int   g_bar[NBLK * 32];              // one flag per 128B line
__device__ __align__(128) int g_epoch[32];      // single-writer epoch line
__device__ __align__(16) __nv_bfloat16 g_hsh[NTY * NB * NH];
__device__ __align__(16) __nv_bfloat16 g_hsl[NTY * NB * NH];
__device__ __align__(16) __nv_bfloat16 g_wth[(long)NV * NH];
__device__ __align__(16) __nv_bfloat16 g_wtl[(long)NV * NH];

// ---------------- helpers ----------------------------------------------------
__device__ __forceinline__ uint32_t smem_u32(const void* p) {
    uint32_t a;
    asm("{ .reg .u64 t; cvta.to.shared.u64 t, %1; cvt.u32.u64 %0, t; }"
        : "=r"(a) : "l"(p));
    return a;
}
__device__ __forceinline__ void ldsm4(uint32_t* r, uint32_t addr) {
    asm volatile("ldmatrix.sync.aligned.m8n8.x4.shared.b16 {%0,%1,%2,%3}, [%4];"
                 : "=r"(r[0]), "=r"(r[1]), "=r"(r[2]), "=r"(r[3]) : "r"(addr));
}
__device__ __forceinline__ void mma16816(float* c, const uint32_t* a,
                                         const uint32_t* b) {
    asm volatile(
        "mma.sync.aligned.m16n8k16.row.col.f32.bf16.bf16.f32 "
        "{%0,%1,%2,%3}, {%4,%5,%6,%7}, {%8,%9}, {%0,%1,%2,%3};"
        : "+f"(c[0]), "+f"(c[1]), "+f"(c[2]), "+f"(c[3])
        : "r"(a[0]), "r"(a[1]), "r"(a[2]), "r"(a[3]), "r"(b[0]), "r"(b[1]));
}
__device__ __forceinline__ void cp16(uint32_t dst, const void* src, int sz) {
    asm volatile("cp.async.cg.shared.global [%0], [%1], 16, %2;"
                 :: "r"(dst), "l"(src), "r"(sz));
}
__device__ __forceinline__ float sigm(float x) { return 1.f / (1.f + expf(-x)); }
__device__ __forceinline__ int ld_acq(const int* p) {
    int v; asm volatile("ld.acquire.gpu.global.s32 %0, [%1];" : "=r"(v) : "l"(p)); return v;
}
__device__ __forceinline__ void st_rel(int* p, int v) {
    asm volatile("st.release.gpu.global.s32 [%0], %1;" :: "l"(p), "r"(v) : "memory");
}

__global__ void init_state() {
    int i = blockIdx.x * blockDim.x + threadIdx.x;
    if (i < 2 * NH * NB) g_ht[i] = 0.f;
    if (i < NBLK * 32)   g_bar[i] = 0;
    if (i == 0)          g_epoch[0] = 0;
}

// ---------------- W_proj transpose + bf16 hi/lo split ------------------------
__global__ void __launch_bounds__(256) wsplit(const float* __restrict__ W) {
    __shared__ float tile[32][33];
    int v0 = blockIdx.x * 32, k0 = blockIdx.y * 32;
    int tx = threadIdx.x & 31, ty = threadIdx.x >> 5;
    #pragma unroll
    for (int i = 0; i < 4; i++) {
        int k = k0 + ty + i * 8, v = v0 + tx;
        tile[ty + i * 8][tx] = (v < NV) ? W[(long)k * NV + v] : 0.f;
    }
    __syncthreads();
    #pragma unroll
    for (int i = 0; i < 4; i++) {
        int v = v0 + ty + i * 8;
        if (v < NV) {
            float x = tile[tx][ty + i * 8];
            __nv_bfloat16 h = __float2bfloat16(x);
            float r = x - __bfloat162float(h);
            g_wth[(long)v * NH + k0 + tx] = h;
            g_wtl[(long)v * NH + k0 + tx] = __float2bfloat16(r);
        }
    }
}

// ---------------- persistent LSTM recurrence ---------------------------------
// R11/R15 structure; ONLY change: hierarchical grid barrier.
// Blocks publish spread flags as before. Block 0 polls all 128 flags, then
// release-publishes ONE epoch word; blocks 1..127 poll only that line with a
// single thread. Poll traffic drops ~100x; single writer => no invalidation
// storm (the R10 failure mode). Acquire->release chaining via block 0 gives
// transitive visibility of every block's h-stores.
__global__ void __launch_bounds__(256, 1) lstm_persist(
    const int* __restrict__ enc_in, const int* __restrict__ dec_in,
    const float* __restrict__ E,
    const float* __restrict__ W_enc, const float* __restrict__ b_enc,
    const float* __restrict__ W_dec, const float* __restrict__ b_dec,
    const int* __restrict__ len)
{
    __shared__ __align__(16) float2 wpen[128][8];
    __shared__ __align__(16) float2 wpdc[128][8];
    __shared__ __align__(16) float2 wxen[64][8];
    __shared__ __align__(16) float2 wxdc[64][8];
    __shared__ float psum[8 * 256];

    int tid  = threadIdx.x;
    int bk   = blockIdx.x;
    int lane = tid & 31;
    int w    = tid >> 5;
    int u0   = bk * 2;

    for (int i = tid; i < 2048; i += 256) {
        int k = i >> 3, c = i & 7;
        int gcol = (c >> 1) * NH + u0 + (c & 1);
        float ve = W_enc[(long)(ND + k) * NG4 + gcol];
        float vd = W_dec[(long)(ND + k) * NG4 + gcol];
        if (k & 1) { wpen[k >> 1][c].y = ve; wpdc[k >> 1][c].y = vd; }
        else       { wpen[k >> 1][c].x = ve; wpdc[k >> 1][c].x = vd; }
    }
    for (int i = tid; i < 1024; i += 256) {
        int k = i >> 3, c = i & 7;
        int gcol = (c >> 1) * NH + u0 + (c & 1);
        float ve = W_enc[(long)k * NG4 + gcol];
        float vd = W_dec[(long)k * NG4 + gcol];
        if (k & 1) { wxen[k >> 1][c].y = ve; wxdc[k >> 1][c].y = vd; }
        else       { wxen[k >> 1][c].x = ve; wxdc[k >> 1][c].x = vd; }
    }

    float creg = 0.f, hreg = 0.f;
    int ul = tid >> 5;
    int bb = tid & 31;
    int mylen = 0;
    float be_i = 0.f, be_j = 0.f, be_f = 0.f, be_o = 0.f;
    float bd_i = 0.f, bd_j = 0.f, bd_f = 0.f, bd_o = 0.f;
    if (tid < 64) {
        mylen = len[bb];
        int u = u0 + ul;
        be_i = b_enc[0 * NH + u]; be_j = b_enc[1 * NH + u];
        be_f = b_enc[2 * NH + u]; be_o = b_enc[3 * NH + u];
        bd_i = b_dec[0 * NH + u]; bd_j = b_dec[1 * NH + u];
        bd_f = b_dec[2 * NH + u]; bd_o = b_dec[3 * NH + u];
    }

    // embedding prefetch for step 0
    float evc[16];
    {
        int tok0 = __ldg(&enc_in[lane * NTX + 0]);
        const float4* er = reinterpret_cast<const float4*>(
            E + (long)tok0 * ND + w * 16);
        float4 e0 = __ldg(er), e1 = __ldg(er + 1);
        float4 e2 = __ldg(er + 2), e3 = __ldg(er + 3);
        evc[0]=e0.x; evc[1]=e0.y; evc[2]=e0.z; evc[3]=e0.w;
        evc[4]=e1.x; evc[5]=e1.y; evc[6]=e1.z; evc[7]=e1.w;
        evc[8]=e2.x; evc[9]=e2.y; evc[10]=e2.z; evc[11]=e2.w;
        evc[12]=e3.x; evc[13]=e3.y; evc[14]=e3.z; evc[15]=e3.w;
    }

    __syncthreads();

    for (int s = 0; s < NSTEPS; s++) {
        int p = s & 1;
        int is_enc = (s < NTX);
        int t = is_enc ? s : s - NTX;

        // ---- issue NEXT step's embedding gather ----
        float evn[16];
        if (s + 1 < NSTEPS) {
            int sn = s + 1;
            int ie = (sn < NTX);
            int tn = ie ? sn : sn - NTX;
            const int* tk = ie ? enc_in : dec_in;
            int Tn = ie ? NTX : NTY;
            int tokn = __ldg(&tk[lane * Tn + tn]);
            const float4* er = reinterpret_cast<const float4*>(
                E + (long)tokn * ND + w * 16);
            float4 e0 = __ldg(er), e1 = __ldg(er + 1);
            float4 e2 = __ldg(er + 2), e3 = __ldg(er + 3);
            evn[0]=e0.x; evn[1]=e0.y; evn[2]=e0.z; evn[3]=e0.w;
            evn[4]=e1.x; evn[5]=e1.y; evn[6]=e1.z; evn[7]=e1.w;
            evn[8]=e2.x; evn[9]=e2.y; evn[10]=e2.z; evn[11]=e2.w;
            evn[12]=e3.x; evn[13]=e3.y; evn[14]=e3.z; evn[15]=e3.w;
        }

        // ---- x-part FMAs from registers ----
        unsigned long long acc2[8];
        #pragma unroll
        for (int c = 0; c < 8; c++) acc2[c] = 0ull;

        const ulonglong2* xrow = is_enc
            ? reinterpret_cast<const ulonglong2*>(&wxen[0][0])
            : reinterpret_cast<const ulonglong2*>(&wxdc[0][0]);
        #pragma unroll
        for (int kp = 0; kp < 8; kp++) {
            unsigned long long a2;
            asm("mov.b64 %0, {%1, %2};" : "=l"(a2)
                : "f"(evc[2 * kp]), "f"(evc[2 * kp + 1]));
            int gkp = w * 8 + kp;
            #pragma unroll
            for (int j = 0; j < 4; j++) {
                ulonglong2 q = xrow[gkp * 4 + j];
                asm("fma.rn.f32x2 %0, %1, %2, %3;"
                    : "=l"(acc2[2 * j]) : "l"(a2), "l"(q.x), "l"(acc2[2 * j]));
                asm("fma.rn.f32x2 %0, %1, %2, %3;"
                    : "=l"(acc2[2 * j + 1]) : "l"(a2), "l"(q.y), "l"(acc2[2 * j + 1]));
            }
        }

        // ---- hierarchical grid barrier ----
        if (s > 0) {
            if (bk == 0) {
                if (tid < NBLK) {
                    while (ld_acq(&g_bar[tid * 32]) < s) { __nanosleep(32); }
                }
                __syncthreads();
                if (tid == 0) st_rel(&g_epoch[0], s);
            } else {
                if (tid == 0) {
                    while (ld_acq(&g_epoch[0]) < s) { }
                }
                __syncthreads();
            }
        }

        // ---- h-part ----
        const float* hsrc = g_ht + (long)p * NH * NB;
        float hv[32];
        #pragma unroll
        for (int k = 0; k < 32; k++)
            hv[k] = __ldcg(hsrc + (w * 32 + k) * NB + lane);

        const ulonglong2* wrow = is_enc
            ? reinterpret_cast<const ulonglong2*>(&wpen[0][0])
            : reinterpret_cast<const ulonglong2*>(&wpdc[0][0]);
        #pragma unroll
        for (int kp = 0; kp < 16; kp++) {
            unsigned long long a2;
            asm("mov.b64 %0, {%1, %2};" : "=l"(a2)
                : "f"(hv[2 * kp]), "f"(hv[2 * kp + 1]));
            int gkp = w * 16 + kp;
            #pragma unroll
            for (int j = 0; j < 4; j++) {
                ulonglong2 q = wrow[gkp * 4 + j];
                asm("fma.rn.f32x2 %0, %1, %2, %3;"
                    : "=l"(acc2[2 * j]) : "l"(a2), "l"(q.x), "l"(acc2[2 * j]));
                asm("fma.rn.f32x2 %0, %1, %2, %3;"
                    : "=l"(acc2[2 * j + 1]) : "l"(a2), "l"(q.y), "l"(acc2[2 * j + 1]));
            }
        }
        #pragma unroll
        for (int c = 0; c < 8; c++) {
            float lo = __uint_as_float((unsigned)(acc2[c] & 0xffffffffull));
            float hi = __uint_as_float((unsigned)(acc2[c] >> 32));
            psum[w * 256 + c * 32 + lane] = lo + hi;
        }
        __syncthreads();

        // ---- finalize ----
        if (tid < 64) {
            float zi, zj, zf, zo;
            if (is_enc) { zi = be_i; zj = be_j; zf = be_f; zo = be_o; }
            else        { zi = bd_i; zj = bd_j; zf = bd_f; zo = bd_o; }
            #pragma unroll
            for (int ww = 0; ww < 8; ww++) {
                zi += psum[ww * 256 + (0 + ul) * 32 + bb];
                zj += psum[ww * 256 + (2 + ul) * 32 + bb];
                zf += psum[ww * 256 + (4 + ul) * 32 + bb];
                zo += psum[ww * 256 + (6 + ul) * 32 + bb];
            }
            float nc = creg * sigm(zf + 1.f) + sigm(zi) * tanhf(zj);
            float nh = tanhf(nc) * sigm(zo);
            if (is_enc && t >= mylen) { nc = creg; nh = hreg; }
            creg = nc; hreg = nh;
            int u = u0 + ul;
            g_ht[(long)(p ^ 1) * NH * NB + (long)u * NB + bb] = nh;
            if (!is_enc) {
                __nv_bfloat16 hh = __float2bfloat16(nh);
                float rr = nh - __bfloat162float(hh);
                long mrow = (long)t * NB + bb;
                g_hsh[mrow * NH + u] = hh;
                g_hsl[mrow * NH + u] = __float2bfloat16(rr);
            }
        }
        __syncthreads();
        if (tid == 0) st_rel(&g_bar[bk * 32], s + 1);

        // rotate embedding pipeline
        #pragma unroll
        for (int i = 0; i < 16; i++) evc[i] = evn[i];
    }
}

// ---------------- projection: warp-private B + cross-tile pipeline (R15) ----
extern __shared__ __align__(16) char proj_sm[];
__global__ void __launch_bounds__(256, 1) proj_mma(float* __restrict__ out)
{
    uint32_t sbase = smem_u32(proj_sm);
    int tid  = threadIdx.x;
    int lane = tid & 31;
    int wid  = tid >> 5;
    int wm   = wid >> 2;
    int wn   = wid & 3;
    int row0 = blockIdx.x * MT;
    int ng   = blockIdx.y;

    for (int i = tid; i < 8192; i += 256) {
        int s = i >> 12, w = i & 4095, row = w >> 5, kseg = w & 31;
        const __nv_bfloat16* src = s ? g_hsl : g_hsh;
        uint4 v = *reinterpret_cast<const uint4*>(
            src + (long)(row0 + row) * NH + kseg * 8);
        *reinterpret_cast<uint4*>(proj_sm + s * ASPLIT + row * APITCH + kseg * 16) = v;
    }
    __syncthreads();

    uint32_t aBase = sbase + (wm * 64 + (lane & 15)) * APITCH + ((lane >> 4) * 8) * 2;
    uint32_t warpB = sbase + B_OFF + wid * BWARP;
    uint32_t bThr  = ((lane & 7) + ((lane >> 4) << 3)) * BROWP
                   + (((lane >> 3) & 1) * 8) * 2;

    auto loadB = [&](int vb, int c, int buf) {
        #pragma unroll
        for (int q = 0; q < 8; q++) {
            int s = q >> 2;
            int i = lane + 32 * (q & 3);
            int row = i >> 2, seg = i & 3;
            int gv = vb + row;
            int cgv = gv < NV ? gv : NV - 1;
            const __nv_bfloat16* src =
                (s ? g_wtl : g_wth) + (long)cgv * NH + c * 32 + seg * 8;
            uint32_t dst = warpB + buf * (2 * BSEG) + s * BSEG
                         + row * BROWP + seg * 16;
            cp16(dst, src, gv < NV ? 16 : 0);
        }
        asm volatile("cp.async.commit_group;" ::: "memory");
    };

    {
        int vb0 = ng * NT + wn * 32;
        loadB(vb0, 0, 0);
        loadB(vb0, 1, 1);
    }

    for (int nt = ng; nt < NNT; nt += NGP) {
        int vbase = nt * NT + wn * 32;
        int hasnext = (nt + NGP) < NNT;
        int vnext = (nt + NGP) * NT + wn * 32;

        float acc[4][4][4];
        #pragma unroll
        for (int a = 0; a < 4; a++)
            #pragma unroll
            for (int b = 0; b < 4; b++)
                #pragma unroll
                for (int c = 0; c < 4; c++) acc[a][b][c] = 0.f;

        #pragma unroll 1
        for (int c = 0; c < 8; c++) {
            if (c == 7 && !hasnext) {
                asm volatile("cp.async.wait_group 0;" ::: "memory");
            } else {
                asm volatile("cp.async.wait_group 1;" ::: "memory");
            }
            __syncwarp();

            int buf = c & 1;
            uint32_t bufH = warpB + buf * (2 * BSEG) + bThr;
            uint32_t bufL = bufH + BSEG;

            #pragma unroll
            for (int kk = 0; kk < 2; kk++) {
                int kg = c * 32 + kk * 16;
                int kl = kk * 32;
                uint32_t ah[4][4], al[4][4];
                #pragma unroll
                for (int mt = 0; mt < 4; mt++) {
                    ldsm4(ah[mt], aBase + mt * (16 * APITCH) + kg * 2);
                    ldsm4(al[mt], aBase + ASPLIT + mt * (16 * APITCH) + kg * 2);
                }
                uint32_t bh[2][4], bl[2][4];
                #pragma unroll
                for (int l = 0; l < 2; l++) {
                    ldsm4(bh[l], bufH + l * (16 * BROWP) + kl);
                    ldsm4(bl[l], bufL + l * (16 * BROWP) + kl);
                }
                #pragma unroll
                for (int mt = 0; mt < 4; mt++) {
                    #pragma unroll
                    for (int ntl = 0; ntl < 4; ntl++) {
                        int l = ntl >> 1, p = (ntl & 1) * 2;
                        uint32_t bhf[2] = {bh[l][p], bh[l][p + 1]};
                        uint32_t blf[2] = {bl[l][p], bl[l][p + 1]};
                        mma16816(acc[mt][ntl], ah[mt], bhf);
                        mma16816(acc[mt][ntl], ah[mt], blf);
                        mma16816(acc[mt][ntl], al[mt], bhf);
                    }
                }
            }
            if (c + 2 < 8) {
                loadB(vbase, c + 2, buf);
            } else if (hasnext) {
                loadB(vnext, c + 2 - 8, buf);
            }
        }

        #pragma unroll
        for (int mt = 0; mt < 4; mt++) {
            int r0 = row0 + wm * 64 + mt * 16 + (lane >> 2);
            int r1 = r0 + 8;
            int tt0 = r0 >> 5, bb0 = r0 & 31;
            int tt1 = r1 >> 5, bb1 = r1 & 31;
            float* o0 = out + (long)bb0 * NTY * NV + (long)tt0 * NV;
            float* o1 = out + (long)bb1 * NTY * NV + (long)tt1 * NV;
            #pragma unroll
            for (int ntl = 0; ntl < 4; ntl++) {
                int cc = vbase + ntl * 8 + 2 * (lane & 3);
                if (cc < NV) {
                    float2 v0 = make_float2(acc[mt][ntl][0], acc[mt][ntl][1]);
                    float2 v1 = make_float2(acc[mt][ntl][2], acc[mt][ntl][3]);
                    *reinterpret_cast<float2*>(o0 + cc) = v0;
                    *reinterpret_cast<float2*>(o1 + cc) = v1;
                }
            }
        }
    }
}

// ---------------- launch ----------------------------------------------------
extern "C" void kernel_launch(void* const* d_in, const int* in_sizes, int n_in,
                              void* d_out, int out_size)
{
    const int*   enc_in = (const int*)d_in[0];
    const int*   dec_in = (const int*)d_in[1];
    const int*   len    = (const int*)d_in[2];
    const float* E      = (const float*)d_in[3];
    const float* W_enc  = (const float*)d_in[4];
    const float* b_enc  = (const float*)d_in[5];
    const float* W_dec  = (const float*)d_in[6];
    const float* b_dec  = (const float*)d_in[7];
    const float* W_proj = (const float*)d_in[8];
    float* out = (float*)d_out;

    cudaFuncSetAttribute(proj_mma, cudaFuncAttributeMaxDynamicSharedMemorySize,
                         PROJ_SMEM);

    init_state<<<64, 256>>>();

    wsplit<<<dim3((NV + 31) / 32, 8), 256>>>(W_proj);

    lstm_persist<<<NBLK, 256>>>(enc_in, dec_in, E, W_enc, b_enc,
                                W_dec, b_dec, len);

    proj_mma<<<dim3(NMT, NGP), 256, PROJ_SMEM>>>(out);
}

// round 17
// speedup vs baseline: 1.6296x; 1.6296x over previous
#include <cuda_runtime.h>
#include <cuda_bf16.h>
#include <math.h>
#include <stdint.h>

// Problem dims
#define NB   32
#define NTX  128
#define NTY  64
#define NV   50000
#define ND   128
#define NH   256
#define NG4  1024
#define NSTEPS (NTX + NTY)
#define NBLK 128

// W_proj split tiling (inside lstm)
#define NVT  ((NV + 31) / 32)          // 1563 v-tiles
#define NTILES (NVT * 8)               // 12504 (k-tiles = 256/32 = 8)

// Projection tiling
#define MT   128
#define NT   128
#define NMT  16
#define NNT  ((NV + NT - 1) / NT)     // 391
#define NGP  9                        // 144 CTAs, single wave

// proj smem layout (bytes from dynamic smem base)
#define APITCH    528
#define ASPLIT    (128 * APITCH)
#define B_OFF     (2 * ASPLIT)
#define BROWP     80
#define BSEG      (32 * BROWP)
#define BWARP     (4 * BSEG)
#define PROJ_SMEM (B_OFF + 8 * BWARP) // 217088

// ---------------- scratch (device globals) ----------------------------------
__device__ float g_ht[2 * NH * NB];
__device__ int   g_bar[NBLK * 32];          // one flag per 128B line (proven)
__device__ __align__(16) __nv_bfloat16 g_hsh[NTY * NB * NH];
__device__ __align__(16) __nv_bfloat16 g_hsl[NTY * NB * NH];
__device__ __align__(16) __nv_bfloat16 g_wth[(long)NV * NH];
__device__ __align__(16) __nv_bfloat16 g_wtl[(long)NV * NH];

// ---------------- helpers ----------------------------------------------------
__device__ __forceinline__ uint32_t smem_u32(const void* p) {
    uint32_t a;
    asm("{ .reg .u64 t; cvta.to.shared.u64 t, %1; cvt.u32.u64 %0, t; }"
        : "=r"(a) : "l"(p));
    return a;
}
__device__ __forceinline__ void ldsm4(uint32_t* r, uint32_t addr) {
    asm volatile("ldmatrix.sync.aligned.m8n8.x4.shared.b16 {%0,%1,%2,%3}, [%4];"
                 : "=r"(r[0]), "=r"(r[1]), "=r"(r[2]), "=r"(r[3]) : "r"(addr));
}
__device__ __forceinline__ void mma16816(float* c, const uint32_t* a,
                                         const uint32_t* b) {
    asm volatile(
        "mma.sync.aligned.m16n8k16.row.col.f32.bf16.bf16.f32 "
        "{%0,%1,%2,%3}, {%4,%5,%6,%7}, {%8,%9}, {%0,%1,%2,%3};"
        : "+f"(c[0]), "+f"(c[1]), "+f"(c[2]), "+f"(c[3])
        : "r"(a[0]), "r"(a[1]), "r"(a[2]), "r"(a[3]), "r"(b[0]), "r"(b[1]));
}
__device__ __forceinline__ void cp16(uint32_t dst, const void* src, int sz) {
    asm volatile("cp.async.cg.shared.global [%0], [%1], 16, %2;"
                 :: "r"(dst), "l"(src), "r"(sz));
}
__device__ __forceinline__ float sigm(float x) { return 1.f / (1.f + expf(-x)); }
__device__ __forceinline__ int ld_acq(const int* p) {
    int v; asm volatile("ld.acquire.gpu.global.s32 %0, [%1];" : "=r"(v) : "l"(p)); return v;
}
__device__ __forceinline__ void st_rel(int* p, int v) {
    asm volatile("st.release.gpu.global.s32 [%0], %1;" :: "l"(p), "r"(v) : "memory");
}

__global__ void init_state() {
    int i = blockIdx.x * blockDim.x + threadIdx.x;
    if (i < 2 * NH * NB) g_ht[i] = 0.f;
    if (i < NBLK * 32)   g_bar[i] = 0;
}

// ---------------- persistent LSTM recurrence ---------------------------------
// R11/R15 proven structure (frozen). NEW: W_proj transpose + bf16 hi/lo split
// folded in, one 32x32 tile per (block, step), finished by step 98:
//   step top : 4 coalesced W row-loads into regs (before poll, hidden);
//              previous step's staged tile -> transposed coalesced store
//   finalize : stage this tile into smem (separated from next read by the
//              trailing __syncthreads, and from this step's read by the
//              psum __syncthreads)
__global__ void __launch_bounds__(256, 1) lstm_persist(
    const int* __restrict__ enc_in, const int* __restrict__ dec_in,
    const float* __restrict__ E,
    const float* __restrict__ W_enc, const float* __restrict__ b_enc,
    const float* __restrict__ W_dec, const float* __restrict__ b_dec,
    const int* __restrict__ len, const float* __restrict__ Wp)
{
    __shared__ __align__(16) float2 wpen[128][8];
    __shared__ __align__(16) float2 wpdc[128][8];
    __shared__ __align__(16) float2 wxen[64][8];
    __shared__ __align__(16) float2 wxdc[64][8];
    __shared__ float psum[8 * 256];
    __shared__ float wtile[32][33];

    int tid  = threadIdx.x;
    int bk   = blockIdx.x;
    int lane = tid & 31;
    int w    = tid >> 5;
    int u0   = bk * 2;

    for (int i = tid; i < 2048; i += 256) {
        int k = i >> 3, c = i & 7;
        int gcol = (c >> 1) * NH + u0 + (c & 1);
        float ve = W_enc[(long)(ND + k) * NG4 + gcol];
        float vd = W_dec[(long)(ND + k) * NG4 + gcol];
        if (k & 1) { wpen[k >> 1][c].y = ve; wpdc[k >> 1][c].y = vd; }
        else       { wpen[k >> 1][c].x = ve; wpdc[k >> 1][c].x = vd; }
    }
    for (int i = tid; i < 1024; i += 256) {
        int k = i >> 3, c = i & 7;
        int gcol = (c >> 1) * NH + u0 + (c & 1);
        float ve = W_enc[(long)k * NG4 + gcol];
        float vd = W_dec[(long)k * NG4 + gcol];
        if (k & 1) { wxen[k >> 1][c].y = ve; wxdc[k >> 1][c].y = vd; }
        else       { wxen[k >> 1][c].x = ve; wxdc[k >> 1][c].x = vd; }
    }

    float creg = 0.f, hreg = 0.f;
    int ul = tid >> 5;
    int bb = tid & 31;
    int mylen = 0;
    float be_i = 0.f, be_j = 0.f, be_f = 0.f, be_o = 0.f;
    float bd_i = 0.f, bd_j = 0.f, bd_f = 0.f, bd_o = 0.f;
    if (tid < 64) {
        mylen = len[bb];
        int u = u0 + ul;
        be_i = b_enc[0 * NH + u]; be_j = b_enc[1 * NH + u];
        be_f = b_enc[2 * NH + u]; be_o = b_enc[3 * NH + u];
        bd_i = b_dec[0 * NH + u]; bd_j = b_dec[1 * NH + u];
        bd_f = b_dec[2 * NH + u]; bd_o = b_dec[3 * NH + u];
    }

    // embedding prefetch for step 0
    float evc[16];
    {
        int tok0 = __ldg(&enc_in[lane * NTX + 0]);
        const float4* er = reinterpret_cast<const float4*>(
            E + (long)tok0 * ND + w * 16);
        float4 e0 = __ldg(er), e1 = __ldg(er + 1);
        float4 e2 = __ldg(er + 2), e3 = __ldg(er + 3);
        evc[0]=e0.x; evc[1]=e0.y; evc[2]=e0.z; evc[3]=e0.w;
        evc[4]=e1.x; evc[5]=e1.y; evc[6]=e1.z; evc[7]=e1.w;
        evc[8]=e2.x; evc[9]=e2.y; evc[10]=e2.z; evc[11]=e2.w;
        evc[12]=e3.x; evc[13]=e3.y; evc[14]=e3.z; evc[15]=e3.w;
    }

    int pv0 = -1, pk0 = 0;   // previous step's staged tile coords

    __syncthreads();

    for (int s = 0; s < NSTEPS; s++) {
        int p = s & 1;
        int is_enc = (s < NTX);
        int t = is_enc ? s : s - NTX;

        // ---- wsplit tile: coalesced loads for tile tau_s (before poll) ----
        int tau = s * NBLK + bk;
        int tvalid = (tau < NTILES);
        int v0 = (tau % NVT) * 32;
        int k0 = (tau / NVT) * 32;
        float lw[4] = {0.f, 0.f, 0.f, 0.f};
        if (tvalid) {
            int vcol = v0 + lane;
            if (vcol < NV) {
                #pragma unroll
                for (int i = 0; i < 4; i++)
                    lw[i] = __ldg(&Wp[(long)(k0 + w * 4 + i) * NV + vcol]);
            }
        }

        // ---- wsplit tile: transposed store of PREVIOUS step's tile ----
        if (pv0 >= 0) {
            int vl = tid >> 3;
            int v = pv0 + vl;
            if (v < NV) {
                #pragma unroll
                for (int j = 0; j < 4; j++) {
                    int kj = (tid & 7) * 4 + j;
                    float x = wtile[kj][vl];
                    __nv_bfloat16 h = __float2bfloat16(x);
                    g_wth[(long)v * NH + pk0 + kj] = h;
                    g_wtl[(long)v * NH + pk0 + kj] =
                        __float2bfloat16(x - __bfloat162float(h));
                }
            }
        }

        // ---- issue NEXT step's embedding gather ----
        float evn[16];
        if (s + 1 < NSTEPS) {
            int sn = s + 1;
            int ie = (sn < NTX);
            int tn = ie ? sn : sn - NTX;
            const int* tk = ie ? enc_in : dec_in;
            int Tn = ie ? NTX : NTY;
            int tokn = __ldg(&tk[lane * Tn + tn]);
            const float4* er = reinterpret_cast<const float4*>(
                E + (long)tokn * ND + w * 16);
            float4 e0 = __ldg(er), e1 = __ldg(er + 1);
            float4 e2 = __ldg(er + 2), e3 = __ldg(er + 3);
            evn[0]=e0.x; evn[1]=e0.y; evn[2]=e0.z; evn[3]=e0.w;
            evn[4]=e1.x; evn[5]=e1.y; evn[6]=e1.z; evn[7]=e1.w;
            evn[8]=e2.x; evn[9]=e2.y; evn[10]=e2.z; evn[11]=e2.w;
            evn[12]=e3.x; evn[13]=e3.y; evn[14]=e3.z; evn[15]=e3.w;
        }

        // ---- x-part FMAs from registers ----
        unsigned long long acc2[8];
        #pragma unroll
        for (int c = 0; c < 8; c++) acc2[c] = 0ull;

        const ulonglong2* xrow = is_enc
            ? reinterpret_cast<const ulonglong2*>(&wxen[0][0])
            : reinterpret_cast<const ulonglong2*>(&wxdc[0][0]);
        #pragma unroll
        for (int kp = 0; kp < 8; kp++) {
            unsigned long long a2;
            asm("mov.b64 %0, {%1, %2};" : "=l"(a2)
                : "f"(evc[2 * kp]), "f"(evc[2 * kp + 1]));
            int gkp = w * 8 + kp;
            #pragma unroll
            for (int j = 0; j < 4; j++) {
                ulonglong2 q = xrow[gkp * 4 + j];
                asm("fma.rn.f32x2 %0, %1, %2, %3;"
                    : "=l"(acc2[2 * j]) : "l"(a2), "l"(q.x), "l"(acc2[2 * j]));
                asm("fma.rn.f32x2 %0, %1, %2, %3;"
                    : "=l"(acc2[2 * j + 1]) : "l"(a2), "l"(q.y), "l"(acc2[2 * j + 1]));
            }
        }

        // ---- grid barrier (R11 proven: spread flags + nanosleep) ----
        if (s > 0) {
            if (tid < NBLK) {
                while (ld_acq(&g_bar[tid * 32]) < s) { __nanosleep(32); }
            }
            __syncthreads();
        }

        // ---- h-part ----
        const float* hsrc = g_ht + (long)p * NH * NB;
        float hv[32];
        #pragma unroll
        for (int k = 0; k < 32; k++)
            hv[k] = __ldcg(hsrc + (w * 32 + k) * NB + lane);

        const ulonglong2* wrow = is_enc
            ? reinterpret_cast<const ulonglong2*>(&wpen[0][0])
            : reinterpret_cast<const ulonglong2*>(&wpdc[0][0]);
        #pragma unroll
        for (int kp = 0; kp < 16; kp++) {
            unsigned long long a2;
            asm("mov.b64 %0, {%1, %2};" : "=l"(a2)
                : "f"(hv[2 * kp]), "f"(hv[2 * kp + 1]));
            int gkp = w * 16 + kp;
            #pragma unroll
            for (int j = 0; j < 4; j++) {
                ulonglong2 q = wrow[gkp * 4 + j];
                asm("fma.rn.f32x2 %0, %1, %2, %3;"
                    : "=l"(acc2[2 * j]) : "l"(a2), "l"(q.x), "l"(acc2[2 * j]));
                asm("fma.rn.f32x2 %0, %1, %2, %3;"
                    : "=l"(acc2[2 * j + 1]) : "l"(a2), "l"(q.y), "l"(acc2[2 * j + 1]));
            }
        }
        #pragma unroll
        for (int c = 0; c < 8; c++) {
            float lo = __uint_as_float((unsigned)(acc2[c] & 0xffffffffull));
            float hi = __uint_as_float((unsigned)(acc2[c] >> 32));
            psum[w * 256 + c * 32 + lane] = lo + hi;
        }
        __syncthreads();

        // ---- finalize ----
        if (tid < 64) {
            float zi, zj, zf, zo;
            if (is_enc) { zi = be_i; zj = be_j; zf = be_f; zo = be_o; }
            else        { zi = bd_i; zj = bd_j; zf = bd_f; zo = bd_o; }
            #pragma unroll
            for (int ww = 0; ww < 8; ww++) {
                zi += psum[ww * 256 + (0 + ul) * 32 + bb];
                zj += psum[ww * 256 + (2 + ul) * 32 + bb];
                zf += psum[ww * 256 + (4 + ul) * 32 + bb];
                zo += psum[ww * 256 + (6 + ul) * 32 + bb];
            }
            float nc = creg * sigm(zf + 1.f) + sigm(zi) * tanhf(zj);
            float nh = tanhf(nc) * sigm(zo);
            if (is_enc && t >= mylen) { nc = creg; nh = hreg; }
            creg = nc; hreg = nh;
            int u = u0 + ul;
            g_ht[(long)(p ^ 1) * NH * NB + (long)u * NB + bb] = nh;
            if (!is_enc) {
                __nv_bfloat16 hh = __float2bfloat16(nh);
                float rr = nh - __bfloat162float(hh);
                long mrow = (long)t * NB + bb;
                g_hsh[mrow * NH + u] = hh;
                g_hsl[mrow * NH + u] = __float2bfloat16(rr);
            }
        }

        // ---- stage this step's W tile into smem (before trailing barrier) --
        if (tvalid) {
            #pragma unroll
            for (int i = 0; i < 4; i++)
                wtile[w * 4 + i][lane] = lw[i];
            pv0 = v0; pk0 = k0;
        } else {
            pv0 = -1;
        }

        __syncthreads();
        if (tid == 0) st_rel(&g_bar[bk * 32], s + 1);

        // rotate embedding pipeline
        #pragma unroll
        for (int i = 0; i < 16; i++) evc[i] = evn[i];
    }
}

// ---------------- projection: warp-private B + cross-tile pipeline (R15) ----
extern __shared__ __align__(16) char proj_sm[];
__global__ void __launch_bounds__(256, 1) proj_mma(float* __restrict__ out)
{
    uint32_t sbase = smem_u32(proj_sm);
    int tid  = threadIdx.x;
    int lane = tid & 31;
    int wid  = tid >> 5;
    int wm   = wid >> 2;
    int wn   = wid & 3;
    int row0 = blockIdx.x * MT;
    int ng   = blockIdx.y;

    for (int i = tid; i < 8192; i += 256) {
        int s = i >> 12, w = i & 4095, row = w >> 5, kseg = w & 31;
        const __nv_bfloat16* src = s ? g_hsl : g_hsh;
        uint4 v = *reinterpret_cast<const uint4*>(
            src + (long)(row0 + row) * NH + kseg * 8);
        *reinterpret_cast<uint4*>(proj_sm + s * ASPLIT + row * APITCH + kseg * 16) = v;
    }
    __syncthreads();

    uint32_t aBase = sbase + (wm * 64 + (lane & 15)) * APITCH + ((lane >> 4) * 8) * 2;
    uint32_t warpB = sbase + B_OFF + wid * BWARP;
    uint32_t bThr  = ((lane & 7) + ((lane >> 4) << 3)) * BROWP
                   + (((lane >> 3) & 1) * 8) * 2;

    auto loadB = [&](int vb, int c, int buf) {
        #pragma unroll
        for (int q = 0; q < 8; q++) {
            int s = q >> 2;
            int i = lane + 32 * (q & 3);
            int row = i >> 2, seg = i & 3;
            int gv = vb + row;
            int cgv = gv < NV ? gv : NV - 1;
            const __nv_bfloat16* src =
                (s ? g_wtl : g_wth) + (long)cgv * NH + c * 32 + seg * 8;
            uint32_t dst = warpB + buf * (2 * BSEG) + s * BSEG
                         + row * BROWP + seg * 16;
            cp16(dst, src, gv < NV ? 16 : 0);
        }
        asm volatile("cp.async.commit_group;" ::: "memory");
    };

    {
        int vb0 = ng * NT + wn * 32;
        loadB(vb0, 0, 0);
        loadB(vb0, 1, 1);
    }

    for (int nt = ng; nt < NNT; nt += NGP) {
        int vbase = nt * NT + wn * 32;
        int hasnext = (nt + NGP) < NNT;
        int vnext = (nt + NGP) * NT + wn * 32;

        float acc[4][4][4];
        #pragma unroll
        for (int a = 0; a < 4; a++)
            #pragma unroll
            for (int b = 0; b < 4; b++)
                #pragma unroll
                for (int c = 0; c < 4; c++) acc[a][b][c] = 0.f;

        #pragma unroll 1
        for (int c = 0; c < 8; c++) {
            if (c == 7 && !hasnext) {
                asm volatile("cp.async.wait_group 0;" ::: "memory");
            } else {
                asm volatile("cp.async.wait_group 1;" ::: "memory");
            }
            __syncwarp();

            int buf = c & 1;
            uint32_t bufH = warpB + buf * (2 * BSEG) + bThr;
            uint32_t bufL = bufH + BSEG;

            #pragma unroll
            for (int kk = 0; kk < 2; kk++) {
                int kg = c * 32 + kk * 16;
                int kl = kk * 32;
                uint32_t ah[4][4], al[4][4];
                #pragma unroll
                for (int mt = 0; mt < 4; mt++) {
                    ldsm4(ah[mt], aBase + mt * (16 * APITCH) + kg * 2);
                    ldsm4(al[mt], aBase + ASPLIT + mt * (16 * APITCH) + kg * 2);
                }
                uint32_t bh[2][4], bl[2][4];
                #pragma unroll
                for (int l = 0; l < 2; l++) {
                    ldsm4(bh[l], bufH + l * (16 * BROWP) + kl);
                    ldsm4(bl[l], bufL + l * (16 * BROWP) + kl);
                }
                #pragma unroll
                for (int mt = 0; mt < 4; mt++) {
                    #pragma unroll
                    for (int ntl = 0; ntl < 4; ntl++) {
                        int l = ntl >> 1, p = (ntl & 1) * 2;
                        uint32_t bhf[2] = {bh[l][p], bh[l][p + 1]};
                        uint32_t blf[2] = {bl[l][p], bl[l][p + 1]};
                        mma16816(acc[mt][ntl], ah[mt], bhf);
                        mma16816(acc[mt][ntl], ah[mt], blf);
                        mma16816(acc[mt][ntl], al[mt], bhf);
                    }
                }
            }
            if (c + 2 < 8) {
                loadB(vbase, c + 2, buf);
            } else if (hasnext) {
                loadB(vnext, c + 2 - 8, buf);
            }
        }

        #pragma unroll
        for (int mt = 0; mt < 4; mt++) {
            int r0 = row0 + wm * 64 + mt * 16 + (lane >> 2);
            int r1 = r0 + 8;
            int tt0 = r0 >> 5, bb0 = r0 & 31;
            int tt1 = r1 >> 5, bb1 = r1 & 31;
            float* o0 = out + (long)bb0 * NTY * NV + (long)tt0 * NV;
            float* o1 = out + (long)bb1 * NTY * NV + (long)tt1 * NV;
            #pragma unroll
            for (int ntl = 0; ntl < 4; ntl++) {
                int cc = vbase + ntl * 8 + 2 * (lane & 3);
                if (cc < NV) {
                    float2 v0 = make_float2(acc[mt][ntl][0], acc[mt][ntl][1]);
                    float2 v1 = make_float2(acc[mt][ntl][2], acc[mt][ntl][3]);
                    *reinterpret_cast<float2*>(o0 + cc) = v0;
                    *reinterpret_cast<float2*>(o1 + cc) = v1;
                }
            }
        }
    }
}

// ---------------- launch ----------------------------------------------------
extern "C" void kernel_launch(void* const* d_in, const int* in_sizes, int n_in,
                              void* d_out, int out_size)
{
    const int*   enc_in = (const int*)d_in[0];
    const int*   dec_in = (const int*)d_in[1];
    const int*   len    = (const int*)d_in[2];
    const float* E      = (const float*)d_in[3];
    const float* W_enc  = (const float*)d_in[4];
    const float* b_enc  = (const float*)d_in[5];
    const float* W_dec  = (const float*)d_in[6];
    const float* b_dec  = (const float*)d_in[7];
    const float* W_proj = (const float*)d_in[8];
    float* out = (float*)d_out;

    cudaFuncSetAttribute(proj_mma, cudaFuncAttributeMaxDynamicSharedMemorySize,
                         PROJ_SMEM);

    init_state<<<64, 256>>>();

    lstm_persist<<<NBLK, 256>>>(enc_in, dec_in, E, W_enc, b_enc,
                                W_dec, b_dec, len, W_proj);

    proj_mma<<<dim3(NMT, NGP), 256, PROJ_SMEM>>>(out);
}